// round 7
// baseline (speedup 1.0000x reference)
#include <cuda_runtime.h>

#define FULL_MASK 0xFFFFFFFFu

constexpr int BLOCK = 256;
constexpr int ITEMS = 32;                 // per thread, 8x float4
constexpr int TILE  = BLOCK * ITEMS;      // 8192 floats
constexpr int NWARPS = BLOCK / 32;
constexpr int MAX_TILES = 4096;           // 2^25 / 8192

// Lookback descriptors, epoch-tagged so NO clearing pass is needed between
// graph replays. High 32 bits = (epoch << 2) | state, low 32 bits = fp32 bits.
//   state: 0 = invalid (initial zeros), 1 = aggregate, 2 = inclusive.
// A word is INVALID unless its epoch matches the current launch's epoch AND
// state != 0. Tag+value are published in ONE relaxed 64-bit store, so a reader
// can never observe the tag without the matching value.
__device__ unsigned long long g_status[MAX_TILES];
__device__ unsigned int       g_ticket;   // monotonic across replays, never reset

__device__ __forceinline__ unsigned long long ld_status(const unsigned long long* p) {
    unsigned long long v;
    asm volatile("ld.relaxed.gpu.global.u64 %0, [%1];" : "=l"(v) : "l"(p));
    return v;
}
__device__ __forceinline__ void st_status(unsigned long long* p, unsigned long long v) {
    asm volatile("st.relaxed.gpu.global.u64 [%0], %1;" :: "l"(p), "l"(v) : "memory");
}
__device__ __forceinline__ unsigned long long pack_status(unsigned epoch, unsigned state, float val) {
    return ((unsigned long long)((epoch << 2) | state) << 32)
         | (unsigned long long)__float_as_uint(val);
}

__global__ void __launch_bounds__(BLOCK)
scan_kernel(const float* __restrict__ x, float* __restrict__ out, int n, unsigned ntiles) {
    __shared__ float    s_warp[NWARPS];
    __shared__ float    s_prefix;
    __shared__ unsigned s_ticket;

    const int lane = threadIdx.x & 31;
    const int wid  = threadIdx.x >> 5;

    // Ticket: issued in CTA scheduling order -> a tile's predecessors are
    // always resident or retired -> lookback cannot deadlock.
    if (threadIdx.x == 0) s_ticket = atomicAdd(&g_ticket, 1u);
    __syncthreads();
    const unsigned ticket = s_ticket;
    const unsigned epoch  = ticket / ntiles;   // launch id (ntiles tickets/launch)
    const unsigned tile   = ticket % ntiles;   // tile id within this launch
    const size_t base = (size_t)tile * TILE + (size_t)threadIdx.x * ITEMS;

    // ---- Load 32 consecutive floats per thread (8x LDG.128) ----
    float v[ITEMS];
    const bool full_tile = (base + ITEMS) <= (size_t)n;
    if (full_tile) {
        const float4* p = reinterpret_cast<const float4*>(x + base);
        #pragma unroll
        for (int j = 0; j < ITEMS / 4; j++) {
            float4 a = p[j];
            v[4*j+0] = a.x; v[4*j+1] = a.y; v[4*j+2] = a.z; v[4*j+3] = a.w;
        }
    } else {
        #pragma unroll
        for (int i = 0; i < ITEMS; i++)
            v[i] = (base + (size_t)i < (size_t)n) ? x[base + i] : 0.f;
    }

    // ---- Thread-serial inclusive scan ----
    #pragma unroll
    for (int i = 1; i < ITEMS; i++) v[i] += v[i - 1];
    const float tsum = v[ITEMS - 1];

    // ---- Warp inclusive scan of thread sums ----
    float incl = tsum;
    #pragma unroll
    for (int d = 1; d < 32; d <<= 1) {
        float t = __shfl_up_sync(FULL_MASK, incl, d);
        if (lane >= d) incl += t;
    }
    const float texcl = incl - tsum;       // exclusive offset of this thread in warp
    if (lane == 31) s_warp[wid] = incl;    // warp total
    __syncthreads();

    // ---- Warp 0: block scan of warp totals + decoupled lookback ----
    if (wid == 0) {
        float wv = (lane < NWARPS) ? s_warp[lane] : 0.f;
        float wincl = wv;
        #pragma unroll
        for (int d = 1; d < NWARPS; d <<= 1) {
            float t = __shfl_up_sync(FULL_MASK, wincl, d);
            if (lane >= d) wincl += t;
        }
        const float block_agg = __shfl_sync(FULL_MASK, wincl, NWARPS - 1);
        if (lane < NWARPS) s_warp[lane] = wincl - wv;  // exclusive warp offsets

        float prefix = 0.f;
        if (tile == 0) {
            if (lane == 0) st_status(&g_status[0], pack_status(epoch, 2u, block_agg));
        } else {
            if (lane == 0) st_status(&g_status[tile], pack_status(epoch, 1u, block_agg));
            // Warp-parallel lookback: lane l inspects predecessor (wb + l).
            int wb = (int)tile - 32;
            while (true) {
                int pred = wb + lane;
                unsigned state; float val;
                // Spin until the whole 32-wide window is valid for THIS epoch.
                do {
                    if (pred >= 0) {
                        unsigned long long w = ld_status(&g_status[pred]);
                        unsigned tag = (unsigned)(w >> 32);
                        state = ((tag >> 2) == epoch) ? (tag & 3u) : 0u;
                        val   = __uint_as_float((unsigned)(w & 0xFFFFFFFFull));
                    } else { state = 2u; val = 0.f; }
                } while (__any_sync(FULL_MASK, state == 0u));

                unsigned bal = __ballot_sync(FULL_MASK, state == 2u);
                if (bal) {
                    int hi = 31 - __clz(bal);  // nearest INCLUSIVE predecessor
                    float contrib = (lane >= hi) ? val : 0.f;
                    #pragma unroll
                    for (int o = 16; o > 0; o >>= 1)
                        contrib += __shfl_xor_sync(FULL_MASK, contrib, o);
                    prefix += contrib;
                    break;
                } else {
                    float contrib = val;   // all aggregates: consume whole window
                    #pragma unroll
                    for (int o = 16; o > 0; o >>= 1)
                        contrib += __shfl_xor_sync(FULL_MASK, contrib, o);
                    prefix += contrib;
                    wb -= 32;
                }
            }
            if (lane == 0)
                st_status(&g_status[tile], pack_status(epoch, 2u, prefix + block_agg));
        }
        if (lane == 0) s_prefix = prefix;
    }
    __syncthreads();

    // ---- Apply offsets and store (8x STG.128) ----
    const float off = s_prefix + s_warp[wid] + texcl;
    #pragma unroll
    for (int i = 0; i < ITEMS; i++) v[i] += off;

    if (full_tile) {
        float4* q = reinterpret_cast<float4*>(out + base);
        #pragma unroll
        for (int j = 0; j < ITEMS / 4; j++)
            q[j] = make_float4(v[4*j+0], v[4*j+1], v[4*j+2], v[4*j+3]);
    } else {
        #pragma unroll
        for (int i = 0; i < ITEMS; i++)
            if (base + (size_t)i < (size_t)n) out[base + i] = v[i];
    }
}

extern "C" void kernel_launch(void* const* d_in, const int* in_sizes, int n_in,
                              void* d_out, int out_size) {
    const float* x = (const float*)d_in[0];
    float* out = (float*)d_out;
    int n = in_sizes[0];
    unsigned ntiles = (unsigned)((n + TILE - 1) / TILE);
    if (ntiles > MAX_TILES) ntiles = MAX_TILES;  // sized for the fixed N=2^25 problem

    scan_kernel<<<ntiles, BLOCK>>>(x, out, n, ntiles);
}